// round 13
// baseline (speedup 1.0000x reference)
#include <cuda_runtime.h>
#include <math.h>

#define CIN     512
#define NTAB    550            // 10+20+...+100 quadrature points
#define LOG2E   1.4426950408889634f
#define EPSQ    1e-5f
#define NTHR    768            // 24 warps: 16 producer + 8 consumer
#define PWARPS  16
#define RPI     256            // rows per iteration (= consumer lanes)
#define NBLK    152            // one block per SM (GB300: 152 SMs)

__device__ __forceinline__ float ex2f(float x) {
    float r;
    asm("ex2.approx.f32 %0, %1;" : "=f"(r) : "f"(x));
    return r;
}
__device__ __forceinline__ float dot4(float4 a, float4 b) {
    return fmaf(a.x, b.x, fmaf(a.y, b.y, fmaf(a.z, b.z, a.w * b.w)));
}

// ---------------------------------------------------------------------------
// Split-block software pipeline, one 768-thread block per SM.
//   warps 0-15 : producers. Iter i: dual GEMV for 256 rows (16 rows/warp) ->
//                zbuf[i&1]. Row loop uses DEPTH-1 REGISTER PREFETCH: row r+1's
//                four float4 loads are issued BEFORE row r's FMA+shfl
//                reduction, so the ~200cyc reduction chain hides most of the
//                LDG latency (previously ~600cyc exposed per row).
//   warps 16-23: consumers. Iter i: Beta quadrature for iter i-1's rows.
// Weights live in smem (4KB) to free registers for the prefetch buffers.
// ---------------------------------------------------------------------------
__global__ void __launch_bounds__(NTHR)
beta_pipe_kernel(const float* __restrict__ x,
                 const float* __restrict__ Wa, const float* __restrict__ ba,
                 const float* __restrict__ Wb, const float* __restrict__ bb,
                 float* __restrict__ out, int B)
{
    __shared__ float2 tab[NTAB];        // (log t, log1p(-t)) * log2e
    __shared__ float2 zbuf[2][RPI];     // double-buffered logits handoff
    __shared__ float4 wsa[CIN / 4];     // W_alpha as float4 (2KB)
    __shared__ float4 wsb[CIN / 4];     // W_beta  as float4 (2KB)

    const int tid  = threadIdx.x;
    const int lane = tid & 31;
    const int wid  = tid >> 5;

    // ---- stage weights into smem ----
    for (int k = tid; k < CIN / 4; k += NTHR) {
        wsa[k] = reinterpret_cast<const float4*>(Wa)[k];
        wsb[k] = reinterpret_cast<const float4*>(Wb)[k];
    }
    // ---- build quadrature table (row-independent) ----
    for (int k = tid; k < NTAB; k += NTHR) {
        int g = 0, off = 0;                        // grid g: 10(g+1) pts @ off
        while (k >= off + 10 * (g + 1)) { off += 10 * (g + 1); ++g; }
        int n = 10 * (g + 1);
        int j = k - off;
        float bthr = 0.1f * (float)(g + 1);
        float step = (bthr - 2.f * EPSQ) / (float)(n - 1);
        float t = fmaf(step, (float)j, EPSQ);
        tab[k] = make_float2(logf(t) * LOG2E, log1pf(-t) * LOG2E);
    }
    __syncthreads();

    const int rowsPB     = (B + NBLK - 1) / NBLK;        // rows per block
    const int blockStart = blockIdx.x * rowsPB;
    const int nIter      = (rowsPB + RPI - 1) / RPI;     // uniform across blocks
    const float biasa = ba[0], biasb = bb[0];

    for (int it = 0; it <= nIter; ++it) {
        if (wid < PWARPS) {
            // ======================= producer =======================
            if (it < nIter) {
                const int rb = blockStart + it * RPI + wid * 16;
                // prefetch row 0
                float4 p0, p1, p2, p3;
                p0 = p1 = p2 = p3 = make_float4(0.f, 0.f, 0.f, 0.f);
                if (rb < B) {
                    const float4* xr = reinterpret_cast<const float4*>(x)
                                     + (size_t)rb * (CIN / 4);
                    p0 = __ldcs(xr + lane);      p1 = __ldcs(xr + lane + 32);
                    p2 = __ldcs(xr + lane + 64); p3 = __ldcs(xr + lane + 96);
                }
#pragma unroll 1
                for (int r = 0; r < 16; ++r) {
                    // issue next row's loads BEFORE reducing this row
                    float4 q0, q1, q2, q3;
                    q0 = q1 = q2 = q3 = make_float4(0.f, 0.f, 0.f, 0.f);
                    const int nrow = rb + r + 1;
                    if (r < 15 && nrow < B) {
                        const float4* xr = reinterpret_cast<const float4*>(x)
                                         + (size_t)nrow * (CIN / 4);
                        q0 = __ldcs(xr + lane);      q1 = __ldcs(xr + lane + 32);
                        q2 = __ldcs(xr + lane + 64); q3 = __ldcs(xr + lane + 96);
                    }
                    // reduce current row (weights from smem; LDS hides in chain)
                    float sa = (dot4(p0, wsa[lane])      + dot4(p1, wsa[lane + 32]))
                             + (dot4(p2, wsa[lane + 64]) + dot4(p3, wsa[lane + 96]));
                    float sb = (dot4(p0, wsb[lane])      + dot4(p1, wsb[lane + 32]))
                             + (dot4(p2, wsb[lane + 64]) + dot4(p3, wsb[lane + 96]));
#pragma unroll
                    for (int off = 16; off; off >>= 1) {
                        sa += __shfl_xor_sync(0xffffffffu, sa, off);
                        sb += __shfl_xor_sync(0xffffffffu, sb, off);
                    }
                    if (lane == 0)
                        zbuf[it & 1][wid * 16 + r] =
                            make_float2(sa + biasa, sb + biasb);
                    p0 = q0; p1 = q1; p2 = q2; p3 = q3;
                }
            }
        } else if (it > 0) {
            // ======================= consumer =======================
            const int idx = (wid - PWARPS) * 32 + lane;          // 0..255
            const int row = blockStart + (it - 1) * RPI + idx;
            if (row < B) {
                const float2 z = zbuf[(it - 1) & 1][idx];
                const float za = z.x, zb = z.y;
                // stable softplus == jax.nn.softplus
                float spa = (za > 0.f) ? (za + log1pf(expf(-za)))
                                       : log1pf(expf(za));
                float spb = (zb > 0.f) ? (zb + log1pf(expf(-zb)))
                                       : log1pf(expf(zb));
                float alpha = fminf(1.f + spa, 100.f);
                float beta  = fminf(1.f + spb, 100.f);
                float lb = lgammaf(alpha) + lgammaf(beta)
                         - lgammaf(alpha + beta);

                const float a1 = alpha - 1.f;
                const float b1 = beta - 1.f;
                const float c2 = -lb * LOG2E;  // dx & exp(-lbeta) cancel in the
                                               // normalization; keep range-safe
                float cdf[10];
                const float2* tp = tab;        // pointer-walk: reg+imm LDS
#pragma unroll
                for (int g = 0; g < 10; ++g) {
                    const int n = 10 * (g + 1);
                    float s0 = 0.f;
#pragma unroll 10
                    for (int k = 0; k < n; ++k) {
                        float2 uv = tp[k];
                        s0 += ex2f(fmaf(a1, uv.x, fmaf(b1, uv.y, c2)));
                    }
                    cdf[g] = s0;
                    tp += n;
                }

                const float inv = 1.f / cdf[9];     // telescoping total mass
                float* o = out + (size_t)row * 10;
                float prev = 0.f;
#pragma unroll
                for (int g = 0; g < 10; ++g) {
                    o[g] = (cdf[g] - prev) * inv;
                    prev = cdf[g];
                }
            }
        }
        __syncthreads();    // all 24 warps, both roles, every iteration
    }
}

// ---------------------------------------------------------------------------
extern "C" void kernel_launch(void* const* d_in, const int* in_sizes, int n_in,
                              void* d_out, int out_size)
{
    const float* x  = (const float*)d_in[0];
    const float* Wa = (const float*)d_in[1];
    const float* ba = (const float*)d_in[2];
    const float* Wb = (const float*)d_in[3];
    const float* bb = (const float*)d_in[4];

    int B = in_sizes[0] / CIN;
    beta_pipe_kernel<<<NBLK, NTHR>>>(x, Wa, ba, Wb, bb, (float*)d_out, B);
}